// round 1
// baseline (speedup 1.0000x reference)
#include <cuda_runtime.h>
#include <cuda_bf16.h>
#include <math.h>

#define N_TOK 4096
#define D_DIM 1024

// Scratch (allocation-free rule: __device__ globals)
__device__ float g_Q[(size_t)N_TOK * D_DIM];
__device__ float g_K[(size_t)N_TOK * D_DIM];
__device__ float g_V[(size_t)N_TOK * D_DIM];
__device__ float g_S[(size_t)N_TOK * N_TOK];

// ---------------------------------------------------------------------------
// Tiled SGEMM: C[M,Nn] = alpha * A[M,K] @ B   (B is [K,Nn] if !TRANSB, [Nn,K] if TRANSB)
// Tiles: BM=BN=128, BK=8. 256 threads, 8x8 per-thread micro-tile.
// Requires: M,Nn % 128 == 0, K % 8 == 0 (true for all calls here).
// ---------------------------------------------------------------------------
template <bool TRANSB>
__global__ __launch_bounds__(256, 2)
void sgemm_kernel(const float* __restrict__ A, const float* __restrict__ B,
                  float* __restrict__ C, int M, int Nn, int K, float alpha)
{
    __shared__ float As[8][128];
    __shared__ float Bs[8][128];

    const int t  = threadIdx.x;          // 0..255
    const int m0 = blockIdx.y * 128;
    const int n0 = blockIdx.x * 128;

    // A-tile loader coords: 128 rows x 8 cols, one float4 per thread
    const int arow  = t >> 1;            // 0..127
    const int aquad = (t & 1) * 4;       // 0 or 4

    // B-tile (NN) loader coords: 8 rows x 128 cols, one float4 per thread
    const int brow = t >> 5;             // 0..7
    const int bcol = (t & 31) * 4;       // 0..124

    const int ty = t >> 4;               // 0..15 -> row group
    const int tx = t & 15;               // 0..15 -> col group

    float acc[8][8];
#pragma unroll
    for (int i = 0; i < 8; ++i)
#pragma unroll
        for (int j = 0; j < 8; ++j) acc[i][j] = 0.f;

    for (int k0 = 0; k0 < K; k0 += 8) {
        // load A tile (transposed into As[k][row])
        {
            const float4 av = *reinterpret_cast<const float4*>(
                &A[(size_t)(m0 + arow) * K + k0 + aquad]);
            As[aquad + 0][arow] = av.x;
            As[aquad + 1][arow] = av.y;
            As[aquad + 2][arow] = av.z;
            As[aquad + 3][arow] = av.w;
        }
        // load B tile into Bs[k][col]
        if (!TRANSB) {
            const float4 bv = *reinterpret_cast<const float4*>(
                &B[(size_t)(k0 + brow) * Nn + n0 + bcol]);
            *reinterpret_cast<float4*>(&Bs[brow][bcol]) = bv;
        } else {
            // B is [Nn, K]; need Bs[k][j] = B[n0+j][k0+k]
            const float4 bv = *reinterpret_cast<const float4*>(
                &B[(size_t)(n0 + arow) * K + k0 + aquad]);
            Bs[aquad + 0][arow] = bv.x;
            Bs[aquad + 1][arow] = bv.y;
            Bs[aquad + 2][arow] = bv.z;
            Bs[aquad + 3][arow] = bv.w;
        }
        __syncthreads();

#pragma unroll
        for (int k = 0; k < 8; ++k) {
            float a[8], b[8];
#pragma unroll
            for (int i = 0; i < 4; ++i) {
                const float4 v = *reinterpret_cast<const float4*>(&As[k][ty * 8 + i * 4]);
                a[i * 4 + 0] = v.x; a[i * 4 + 1] = v.y; a[i * 4 + 2] = v.z; a[i * 4 + 3] = v.w;
                i++; // (compile-time unrolled; keep simple: two float4 loads)
                const float4 w = *reinterpret_cast<const float4*>(&As[k][ty * 8 + 4]);
                a[4] = w.x; a[5] = w.y; a[6] = w.z; a[7] = w.w;
                break;
            }
            {
                const float4 v = *reinterpret_cast<const float4*>(&Bs[k][tx * 8 + 0]);
                const float4 w = *reinterpret_cast<const float4*>(&Bs[k][tx * 8 + 4]);
                b[0] = v.x; b[1] = v.y; b[2] = v.z; b[3] = v.w;
                b[4] = w.x; b[5] = w.y; b[6] = w.z; b[7] = w.w;
            }
#pragma unroll
            for (int i = 0; i < 8; ++i)
#pragma unroll
                for (int j = 0; j < 8; ++j)
                    acc[i][j] = fmaf(a[i], b[j], acc[i][j]);
        }
        __syncthreads();
    }

    // epilogue
#pragma unroll
    for (int i = 0; i < 8; ++i) {
        float* crow = &C[(size_t)(m0 + ty * 8 + i) * Nn + n0 + tx * 8];
        float4 v0, v1;
        v0.x = alpha * acc[i][0]; v0.y = alpha * acc[i][1];
        v0.z = alpha * acc[i][2]; v0.w = alpha * acc[i][3];
        v1.x = alpha * acc[i][4]; v1.y = alpha * acc[i][5];
        v1.z = alpha * acc[i][6]; v1.w = alpha * acc[i][7];
        *reinterpret_cast<float4*>(crow + 0) = v0;
        *reinterpret_cast<float4*>(crow + 4) = v1;
    }
}

// ---------------------------------------------------------------------------
// Row softmax in place: one block per row, 256 threads, Nn = 4096.
// ---------------------------------------------------------------------------
__global__ __launch_bounds__(256)
void softmax_rows_kernel(float* __restrict__ S, int Nn)
{
    __shared__ float red[32];
    const int row = blockIdx.x;
    float* p = S + (size_t)row * Nn;
    const int t = threadIdx.x;
    const int lane = t & 31, wid = t >> 5;

    // pass 1: max
    float m = -INFINITY;
    for (int i = t * 4; i < Nn; i += 256 * 4) {
        const float4 v = *reinterpret_cast<const float4*>(p + i);
        m = fmaxf(m, fmaxf(fmaxf(v.x, v.y), fmaxf(v.z, v.w)));
    }
#pragma unroll
    for (int o = 16; o > 0; o >>= 1) m = fmaxf(m, __shfl_xor_sync(0xffffffff, m, o));
    if (lane == 0) red[wid] = m;
    __syncthreads();
    if (t < 32) {
        float v = (t < 8) ? red[t] : -INFINITY;
#pragma unroll
        for (int o = 4; o > 0; o >>= 1) v = fmaxf(v, __shfl_xor_sync(0xffffffff, v, o));
        if (t == 0) red[0] = v;
    }
    __syncthreads();
    m = red[0];
    __syncthreads();

    // pass 2: exp + sum
    float s = 0.f;
    for (int i = t * 4; i < Nn; i += 256 * 4) {
        float4 v = *reinterpret_cast<const float4*>(p + i);
        v.x = __expf(v.x - m); v.y = __expf(v.y - m);
        v.z = __expf(v.z - m); v.w = __expf(v.w - m);
        s += v.x + v.y + v.z + v.w;
        *reinterpret_cast<float4*>(p + i) = v;
    }
#pragma unroll
    for (int o = 16; o > 0; o >>= 1) s += __shfl_xor_sync(0xffffffff, s, o);
    if (lane == 0) red[wid] = s;
    __syncthreads();
    if (t < 32) {
        float v = (t < 8) ? red[t] : 0.f;
#pragma unroll
        for (int o = 4; o > 0; o >>= 1) v += __shfl_xor_sync(0xffffffff, v, o);
        if (t == 0) red[0] = v;
    }
    __syncthreads();
    const float inv = 1.f / red[0];

    // pass 3: normalize
    for (int i = t * 4; i < Nn; i += 256 * 4) {
        float4 v = *reinterpret_cast<const float4*>(p + i);
        v.x *= inv; v.y *= inv; v.z *= inv; v.w *= inv;
        *reinterpret_cast<float4*>(p + i) = v;
    }
}

// ---------------------------------------------------------------------------
extern "C" void kernel_launch(void* const* d_in, const int* in_sizes, int n_in,
                              void* d_out, int out_size)
{
    const float* x  = (const float*)d_in[0];
    const float* Wq = (const float*)d_in[1];
    const float* Wk = (const float*)d_in[2];
    const float* Wv = (const float*)d_in[3];
    float* out = (float*)d_out;

    float *Q, *K, *V, *S;
    cudaGetSymbolAddress((void**)&Q, g_Q);
    cudaGetSymbolAddress((void**)&K, g_K);
    cudaGetSymbolAddress((void**)&V, g_V);
    cudaGetSymbolAddress((void**)&S, g_S);

    const dim3 blk(256);

    // QKV projections: [4096,1024] = [4096,1024] @ [1024,1024]
    {
        const dim3 grd(D_DIM / 128, N_TOK / 128);
        sgemm_kernel<false><<<grd, blk>>>(x, Wq, Q, N_TOK, D_DIM, D_DIM, 1.f);
        sgemm_kernel<false><<<grd, blk>>>(x, Wk, K, N_TOK, D_DIM, D_DIM, 1.f);
        sgemm_kernel<false><<<grd, blk>>>(x, Wv, V, N_TOK, D_DIM, D_DIM, 1.f);
    }

    // S = (Q @ K^T) / sqrt(1024)
    {
        const dim3 grd(N_TOK / 128, N_TOK / 128);
        sgemm_kernel<true><<<grd, blk>>>(Q, K, S, N_TOK, N_TOK, D_DIM, 1.f / 32.f);
    }

    // softmax rows in place
    softmax_rows_kernel<<<N_TOK, blk>>>(S, N_TOK);

    // out = P @ V
    {
        const dim3 grd(D_DIM / 128, N_TOK / 128);
        sgemm_kernel<false><<<grd, blk>>>(S, V, out, N_TOK, D_DIM, N_TOK, 1.f);
    }
}

// round 8
// speedup vs baseline: 3.4655x; 3.4655x over previous
#include <cuda_runtime.h>
#include <cuda_bf16.h>
#include <math.h>
#include <cstdint>

#define N_TOK 4096
#define D_DIM 1024

// ------------------------- scratch (__device__ globals) ---------------------
__device__ float g_Q[(size_t)N_TOK * D_DIM];
__device__ float g_K[(size_t)N_TOK * D_DIM];
__device__ float g_V[(size_t)N_TOK * D_DIM];
__device__ float g_S[(size_t)N_TOK * N_TOK];
__device__ float g_Wqt[(size_t)D_DIM * D_DIM];
__device__ float g_Wkt[(size_t)D_DIM * D_DIM];
__device__ float g_Wvt[(size_t)D_DIM * D_DIM];
__device__ float g_Vt[(size_t)D_DIM * N_TOK];

// ------------------------- PTX helpers --------------------------------------
__device__ __forceinline__ uint32_t smem_to_u32(const void* smem_ptr) {
    uint32_t addr;
    asm("{ .reg .u64 tmp; cvta.to.shared.u64 tmp, %1; cvt.u32.u64 %0, tmp; }"
        : "=r"(addr) : "l"(smem_ptr));
    return addr;
}

__device__ __forceinline__ void cp_async16(uint32_t dst_smem, const void* src) {
    asm volatile("cp.async.cg.shared.global [%0], [%1], 16;"
                 :: "r"(dst_smem), "l"(src) : "memory");
}
__device__ __forceinline__ void cp_async_commit() {
    asm volatile("cp.async.commit_group;" ::: "memory");
}
template <int N>
__device__ __forceinline__ void cp_async_wait() {
    asm volatile("cp.async.wait_group %0;" :: "n"(N) : "memory");
}

__device__ __forceinline__ void ldmatrix_x4(uint32_t& r0, uint32_t& r1,
                                            uint32_t& r2, uint32_t& r3,
                                            uint32_t addr) {
    asm volatile("ldmatrix.sync.aligned.m8n8.x4.shared.b16 {%0,%1,%2,%3}, [%4];"
                 : "=r"(r0), "=r"(r1), "=r"(r2), "=r"(r3) : "r"(addr));
}

__device__ __forceinline__ uint32_t f2tf32(uint32_t x) {
    uint32_t o;
    asm("cvt.rna.tf32.f32 %0, %1;" : "=r"(o) : "f"(__uint_as_float(x)));
    return o;
}

__device__ __forceinline__ void mma_tf32(float* c, const uint32_t* a,
                                         uint32_t b0, uint32_t b1) {
    asm volatile(
        "mma.sync.aligned.m16n8k8.row.col.f32.tf32.tf32.f32 "
        "{%0,%1,%2,%3}, {%4,%5,%6,%7}, {%8,%9}, {%0,%1,%2,%3};"
        : "+f"(c[0]), "+f"(c[1]), "+f"(c[2]), "+f"(c[3])
        : "r"(a[0]), "r"(a[1]), "r"(a[2]), "r"(a[3]), "r"(b0), "r"(b1));
}

// ------------------------- smem layout (dynamic, 64KB) -----------------------
// A0 [0,16K), B0 [16K,32K), A1 [32K,48K), B1 [48K,64K)
// tile = 128 rows x 32 f32 = 128B/row, Swizzle<3,4,3>: chunk16 ^= (row&7)
#define GEMM_SMEM_TOTAL 65536

// ---------------------------------------------------------------------------
// tf32 mma.sync GEMM: C[M,Nn] = alpha * A[M,Kd] @ B^T, B is [Nn,Kd] row-major.
// M,Nn % 128 == 0; Kd % 32 == 0. 256 threads. grid = (Nn/128, M/128).
// ---------------------------------------------------------------------------
__global__ __launch_bounds__(256)
void gemm_tf32_mma_kernel(const float* __restrict__ A, const float* __restrict__ B,
                          float* __restrict__ C, int M, int Nn, int Kd, float alpha)
{
    extern __shared__ char smem[];
    const uint32_t sbase = smem_to_u32(smem);
    const int t    = threadIdx.x;
    const int wid  = t >> 5;
    const int lane = t & 31;
    const int warp_m = wid & 1;        // 0..1  -> 64 rows each
    const int warp_n = wid >> 1;       // 0..3  -> 32 cols each
    const int m0 = blockIdx.y * 128;
    const int n0 = blockIdx.x * 128;

    const uint32_t offA[2] = {0u, 32768u};
    const uint32_t offB[2] = {16384u, 49152u};

    float acc[4][4][4];
#pragma unroll
    for (int i = 0; i < 4; ++i)
#pragma unroll
        for (int j = 0; j < 4; ++j)
#pragma unroll
            for (int k = 0; k < 4; ++k) acc[i][j][k] = 0.f;

    // ---- cp.async coords: 4 float4 per operand per thread ----
    uint32_t dstoff[4];
    int grow[4], gcol[4];
#pragma unroll
    for (int i = 0; i < 4; ++i) {
        const int idx = t + i * 256;       // 0..1023
        const int row = idx >> 3;          // 0..127
        const int ch  = idx & 7;           // 0..7 (16B chunks)
        dstoff[i] = row * 128 + ((ch * 16) ^ ((row & 7) << 4));
        grow[i] = row;
        gcol[i] = ch * 4;
    }

    // ---- ldmatrix per-thread base coords ----
    const int sub  = lane >> 3;            // matrix id 0..3
    const int rlo  = ((sub & 1) << 3) + (lane & 7);
    const int csel = sub >> 1;             // chunk offset 0/1

    uint32_t rbA[4], rxA[4];
#pragma unroll
    for (int mt = 0; mt < 4; ++mt) {
        const int row = warp_m * 64 + mt * 16 + rlo;
        rbA[mt] = row * 128;
        rxA[mt] = (row & 7) << 4;
    }
    uint32_t rbB[2], rxB[2];
#pragma unroll
    for (int np = 0; np < 2; ++np) {
        const int row = warp_n * 32 + np * 16 + rlo;
        rbB[np] = row * 128;
        rxB[np] = (row & 7) << 4;
    }

    const int KI = Kd >> 5;

    // prologue: tile 0 -> buf 0
#pragma unroll
    for (int i = 0; i < 4; ++i) {
        cp_async16(sbase + offA[0] + dstoff[i], &A[(size_t)(m0 + grow[i]) * Kd + gcol[i]]);
        cp_async16(sbase + offB[0] + dstoff[i], &B[(size_t)(n0 + grow[i]) * Kd + gcol[i]]);
    }
    cp_async_commit();

    for (int it = 0; it < KI; ++it) {
        const int cur = it & 1;
        const bool more = (it + 1 < KI);
        if (more) {
            const int k0 = (it + 1) << 5;
            const int nxt = cur ^ 1;
#pragma unroll
            for (int i = 0; i < 4; ++i) {
                cp_async16(sbase + offA[nxt] + dstoff[i],
                           &A[(size_t)(m0 + grow[i]) * Kd + k0 + gcol[i]]);
                cp_async16(sbase + offB[nxt] + dstoff[i],
                           &B[(size_t)(n0 + grow[i]) * Kd + k0 + gcol[i]]);
            }
            cp_async_commit();
            cp_async_wait<1>();
        } else {
            cp_async_wait<0>();
        }
        __syncthreads();

        const uint32_t aBase = sbase + offA[cur];
        const uint32_t bBase = sbase + offB[cur];
#pragma unroll
        for (int ks = 0; ks < 4; ++ks) {
            const uint32_t cOff = (uint32_t)((ks * 2 + csel) * 16);
            uint32_t a[4][4], b[2][4];
#pragma unroll
            for (int mt = 0; mt < 4; ++mt)
                ldmatrix_x4(a[mt][0], a[mt][1], a[mt][2], a[mt][3],
                            aBase + rbA[mt] + (cOff ^ rxA[mt]));
#pragma unroll
            for (int np = 0; np < 2; ++np)
                ldmatrix_x4(b[np][0], b[np][1], b[np][2], b[np][3],
                            bBase + rbB[np] + (cOff ^ rxB[np]));
            // tf32 rounding (RNA)
#pragma unroll
            for (int mt = 0; mt < 4; ++mt)
#pragma unroll
                for (int r = 0; r < 4; ++r) a[mt][r] = f2tf32(a[mt][r]);
#pragma unroll
            for (int np = 0; np < 2; ++np)
#pragma unroll
                for (int r = 0; r < 4; ++r) b[np][r] = f2tf32(b[np][r]);

#pragma unroll
            for (int mt = 0; mt < 4; ++mt)
#pragma unroll
                for (int nt = 0; nt < 4; ++nt) {
                    const int np = nt >> 1, pos = nt & 1;
                    mma_tf32(acc[mt][nt], a[mt], b[np][pos], b[np][pos + 2]);
                }
        }
        __syncthreads();
    }

    // ---- epilogue ----
    const int gq = lane >> 2;     // groupID
    const int tg = lane & 3;      // thread in group
#pragma unroll
    for (int mt = 0; mt < 4; ++mt) {
        const int r0 = m0 + warp_m * 64 + mt * 16 + gq;
#pragma unroll
        for (int nt = 0; nt < 4; ++nt) {
            const int c = n0 + warp_n * 32 + nt * 8 + tg * 2;
            float2 v0, v1;
            v0.x = alpha * acc[mt][nt][0]; v0.y = alpha * acc[mt][nt][1];
            v1.x = alpha * acc[mt][nt][2]; v1.y = alpha * acc[mt][nt][3];
            *reinterpret_cast<float2*>(&C[(size_t)r0 * Nn + c]) = v0;
            *reinterpret_cast<float2*>(&C[(size_t)(r0 + 8) * Nn + c]) = v1;
        }
    }
}

// ---------------------------------------------------------------------------
// transpose: out[C][R] = in[R][C]
// ---------------------------------------------------------------------------
__global__ __launch_bounds__(256)
void transpose_kernel(const float* __restrict__ in, float* __restrict__ out,
                      int R, int C)
{
    __shared__ float tile[32][33];
    const int c0 = blockIdx.x * 32;
    const int r0 = blockIdx.y * 32;
    const int tx = threadIdx.x, ty = threadIdx.y;
#pragma unroll
    for (int i = ty; i < 32; i += 8)
        tile[i][tx] = in[(size_t)(r0 + i) * C + c0 + tx];
    __syncthreads();
#pragma unroll
    for (int i = ty; i < 32; i += 8)
        out[(size_t)(c0 + i) * R + r0 + tx] = tile[tx][i];
}

// ---------------------------------------------------------------------------
// Row softmax in place: one block per row, 256 threads, Nn = 4096.
// ---------------------------------------------------------------------------
__global__ __launch_bounds__(256)
void softmax_rows_kernel(float* __restrict__ S, int Nn)
{
    __shared__ float red[32];
    const int row = blockIdx.x;
    float* p = S + (size_t)row * Nn;
    const int t = threadIdx.x;
    const int lane = t & 31, wid = t >> 5;

    float m = -INFINITY;
    for (int i = t * 4; i < Nn; i += 256 * 4) {
        const float4 v = *reinterpret_cast<const float4*>(p + i);
        m = fmaxf(m, fmaxf(fmaxf(v.x, v.y), fmaxf(v.z, v.w)));
    }
#pragma unroll
    for (int o = 16; o > 0; o >>= 1) m = fmaxf(m, __shfl_xor_sync(0xffffffff, m, o));
    if (lane == 0) red[wid] = m;
    __syncthreads();
    if (t < 32) {
        float v = (t < 8) ? red[t] : -INFINITY;
#pragma unroll
        for (int o = 4; o > 0; o >>= 1) v = fmaxf(v, __shfl_xor_sync(0xffffffff, v, o));
        if (t == 0) red[0] = v;
    }
    __syncthreads();
    m = red[0];
    __syncthreads();

    float s = 0.f;
    for (int i = t * 4; i < Nn; i += 256 * 4) {
        float4 v = *reinterpret_cast<const float4*>(p + i);
        v.x = __expf(v.x - m); v.y = __expf(v.y - m);
        v.z = __expf(v.z - m); v.w = __expf(v.w - m);
        s += v.x + v.y + v.z + v.w;
        *reinterpret_cast<float4*>(p + i) = v;
    }
#pragma unroll
    for (int o = 16; o > 0; o >>= 1) s += __shfl_xor_sync(0xffffffff, s, o);
    if (lane == 0) red[wid] = s;
    __syncthreads();
    if (t < 32) {
        float v = (t < 8) ? red[t] : 0.f;
#pragma unroll
        for (int o = 4; o > 0; o >>= 1) v += __shfl_xor_sync(0xffffffff, v, o);
        if (t == 0) red[0] = v;
    }
    __syncthreads();
    const float inv = 1.f / red[0];

    for (int i = t * 4; i < Nn; i += 256 * 4) {
        float4 v = *reinterpret_cast<const float4*>(p + i);
        v.x *= inv; v.y *= inv; v.z *= inv; v.w *= inv;
        *reinterpret_cast<float4*>(p + i) = v;
    }
}

// ---------------------------------------------------------------------------
extern "C" void kernel_launch(void* const* d_in, const int* in_sizes, int n_in,
                              void* d_out, int out_size)
{
    const float* x  = (const float*)d_in[0];
    const float* Wq = (const float*)d_in[1];
    const float* Wk = (const float*)d_in[2];
    const float* Wv = (const float*)d_in[3];
    float* out = (float*)d_out;

    float *Q, *K, *V, *S, *Wqt, *Wkt, *Wvt, *Vt;
    cudaGetSymbolAddress((void**)&Q, g_Q);
    cudaGetSymbolAddress((void**)&K, g_K);
    cudaGetSymbolAddress((void**)&V, g_V);
    cudaGetSymbolAddress((void**)&S, g_S);
    cudaGetSymbolAddress((void**)&Wqt, g_Wqt);
    cudaGetSymbolAddress((void**)&Wkt, g_Wkt);
    cudaGetSymbolAddress((void**)&Wvt, g_Wvt);
    cudaGetSymbolAddress((void**)&Vt, g_Vt);

    cudaFuncSetAttribute(gemm_tf32_mma_kernel,
                         cudaFuncAttributeMaxDynamicSharedMemorySize, GEMM_SMEM_TOTAL);

    const dim3 tblk(32, 8);

    // transpose weights: Wt[d_out][d_in]
    {
        const dim3 tg(D_DIM / 32, D_DIM / 32);
        transpose_kernel<<<tg, tblk>>>(Wq, Wqt, D_DIM, D_DIM);
        transpose_kernel<<<tg, tblk>>>(Wk, Wkt, D_DIM, D_DIM);
        transpose_kernel<<<tg, tblk>>>(Wv, Wvt, D_DIM, D_DIM);
    }

    // QKV projections
    {
        const dim3 g(D_DIM / 128, N_TOK / 128);
        gemm_tf32_mma_kernel<<<g, 256, GEMM_SMEM_TOTAL>>>(x, Wqt, Q, N_TOK, D_DIM, D_DIM, 1.f);
        gemm_tf32_mma_kernel<<<g, 256, GEMM_SMEM_TOTAL>>>(x, Wkt, K, N_TOK, D_DIM, D_DIM, 1.f);
        gemm_tf32_mma_kernel<<<g, 256, GEMM_SMEM_TOTAL>>>(x, Wvt, V, N_TOK, D_DIM, D_DIM, 1.f);
    }

    // Vt[d][token]
    {
        const dim3 tg(D_DIM / 32, N_TOK / 32);
        transpose_kernel<<<tg, tblk>>>(V, Vt, N_TOK, D_DIM);
    }

    // S = (Q @ K^T) / 32
    {
        const dim3 g(N_TOK / 128, N_TOK / 128);
        gemm_tf32_mma_kernel<<<g, 256, GEMM_SMEM_TOTAL>>>(Q, K, S, N_TOK, N_TOK, D_DIM, 1.f / 32.f);
    }

    softmax_rows_kernel<<<N_TOK, 256>>>(S, N_TOK);

    // out = P @ V
    {
        const dim3 g(D_DIM / 128, N_TOK / 128);
        gemm_tf32_mma_kernel<<<g, 256, GEMM_SMEM_TOTAL>>>(S, Vt, out, N_TOK, D_DIM, N_TOK, 1.f);
    }
}

// round 9
// speedup vs baseline: 3.8372x; 1.1073x over previous
#include <cuda_runtime.h>
#include <cuda_bf16.h>
#include <math.h>
#include <cstdint>

#define N_TOK 4096
#define D_DIM 1024

// ------------------------- scratch (__device__ globals) ---------------------
__device__ float g_Xr[(size_t)N_TOK * D_DIM];
__device__ float g_Q[(size_t)N_TOK * D_DIM];
__device__ float g_K[(size_t)N_TOK * D_DIM];
__device__ float g_V[(size_t)N_TOK * D_DIM];
__device__ float g_S[(size_t)N_TOK * N_TOK];
__device__ float g_Wqt[(size_t)D_DIM * D_DIM];
__device__ float g_Wkt[(size_t)D_DIM * D_DIM];
__device__ float g_Wvt[(size_t)D_DIM * D_DIM];
__device__ float g_Vt[(size_t)D_DIM * N_TOK];

// ------------------------- PTX helpers --------------------------------------
__device__ __forceinline__ uint32_t smem_to_u32(const void* smem_ptr) {
    uint32_t addr;
    asm("{ .reg .u64 tmp; cvta.to.shared.u64 tmp, %1; cvt.u32.u64 %0, tmp; }"
        : "=r"(addr) : "l"(smem_ptr));
    return addr;
}

__device__ __forceinline__ void cp_async16(uint32_t dst_smem, const void* src) {
    asm volatile("cp.async.cg.shared.global [%0], [%1], 16;"
                 :: "r"(dst_smem), "l"(src) : "memory");
}
__device__ __forceinline__ void cp_async_commit() {
    asm volatile("cp.async.commit_group;" ::: "memory");
}
template <int N>
__device__ __forceinline__ void cp_async_wait() {
    asm volatile("cp.async.wait_group %0;" :: "n"(N) : "memory");
}

__device__ __forceinline__ void ldmatrix_x4(uint32_t& r0, uint32_t& r1,
                                            uint32_t& r2, uint32_t& r3,
                                            uint32_t addr) {
    asm volatile("ldmatrix.sync.aligned.m8n8.x4.shared.b16 {%0,%1,%2,%3}, [%4];"
                 : "=r"(r0), "=r"(r1), "=r"(r2), "=r"(r3) : "r"(addr));
}

__device__ __forceinline__ float roundtf(float x) {
    uint32_t o;
    asm("cvt.rna.tf32.f32 %0, %1;" : "=r"(o) : "f"(x));
    return __uint_as_float(o);
}

__device__ __forceinline__ void mma_tf32(float* c, const uint32_t* a,
                                         uint32_t b0, uint32_t b1) {
    asm volatile(
        "mma.sync.aligned.m16n8k8.row.col.f32.tf32.tf32.f32 "
        "{%0,%1,%2,%3}, {%4,%5,%6,%7}, {%8,%9}, {%0,%1,%2,%3};"
        : "+f"(c[0]), "+f"(c[1]), "+f"(c[2]), "+f"(c[3])
        : "r"(a[0]), "r"(a[1]), "r"(a[2]), "r"(a[3]), "r"(b0), "r"(b1));
}

// ------------------------- smem layout (dynamic, 96KB, 3 stages) -------------
// stage s at s*32768: A at +0 (16KB), B at +16384 (16KB)
// tile = 128 rows x 32 f32 = 128B/row, Swizzle: chunk16 ^= (row&7)
#define GEMM_SMEM_TOTAL (3 * 32768)

// ---------------------------------------------------------------------------
// tf32 mma.sync GEMM: C[M,Nn] = alpha * A[M,Kd] @ B^T, B is [Nn,Kd] row-major.
// All operand matrices MUST already be tf32-rounded (low 13 mantissa bits 0).
// Batched over blockIdx.z: B/C pointers selected from arg triple.
// M,Nn % 128 == 0; Kd % 32 == 0. 256 threads. grid = (Nn/128, M/128, nb).
// ---------------------------------------------------------------------------
template <bool ROUND_OUT>
__global__ __launch_bounds__(256)
void gemm_tf32_mma_kernel(const float* __restrict__ A,
                          const float* __restrict__ B0,
                          const float* __restrict__ B1,
                          const float* __restrict__ B2,
                          float* __restrict__ C0,
                          float* __restrict__ C1,
                          float* __restrict__ C2,
                          int M, int Nn, int Kd, float alpha)
{
    extern __shared__ char smem[];
    const uint32_t sbase = smem_to_u32(smem);
    const int t    = threadIdx.x;
    const int wid  = t >> 5;
    const int lane = t & 31;
    const int warp_m = wid & 1;        // 0..1  -> 64 rows each
    const int warp_n = wid >> 1;       // 0..3  -> 32 cols each
    const int m0 = blockIdx.y * 128;
    const int n0 = blockIdx.x * 128;

    const float* B = (blockIdx.z == 0) ? B0 : (blockIdx.z == 1) ? B1 : B2;
    float*       C = (blockIdx.z == 0) ? C0 : (blockIdx.z == 1) ? C1 : C2;

    float acc[4][4][4];
#pragma unroll
    for (int i = 0; i < 4; ++i)
#pragma unroll
        for (int j = 0; j < 4; ++j)
#pragma unroll
            for (int k = 0; k < 4; ++k) acc[i][j][k] = 0.f;

    // ---- cp.async coords: 4 float4 per operand per thread ----
    uint32_t dstoff[4];
    int grow[4], gcol[4];
#pragma unroll
    for (int i = 0; i < 4; ++i) {
        const int idx = t + i * 256;       // 0..1023
        const int row = idx >> 3;          // 0..127
        const int ch  = idx & 7;           // 0..7 (16B chunks)
        dstoff[i] = row * 128 + ((ch * 16) ^ ((row & 7) << 4));
        grow[i] = row;
        gcol[i] = ch * 4;
    }

    // ---- ldmatrix per-thread base coords ----
    const int sub  = lane >> 3;            // matrix id 0..3
    const int rlo  = ((sub & 1) << 3) + (lane & 7);
    const int csel = sub >> 1;             // chunk offset 0/1

    uint32_t rbA[4], rxA[4];
#pragma unroll
    for (int mt = 0; mt < 4; ++mt) {
        const int row = warp_m * 64 + mt * 16 + rlo;
        rbA[mt] = row * 128;
        rxA[mt] = (row & 7) << 4;
    }
    uint32_t rbB[2], rxB[2];
#pragma unroll
    for (int np = 0; np < 2; ++np) {
        const int row = warp_n * 32 + np * 16 + rlo;
        rbB[np] = row * 128;
        rxB[np] = (row & 7) << 4;
    }

    const int KI = Kd >> 5;

    // prologue: issue tiles 0 and 1 into stages 0 and 1
#pragma unroll
    for (int pt = 0; pt < 2; ++pt) {
        const uint32_t st = sbase + pt * 32768u;
        const int k0 = pt << 5;
#pragma unroll
        for (int i = 0; i < 4; ++i) {
            cp_async16(st + dstoff[i],         &A[(size_t)(m0 + grow[i]) * Kd + k0 + gcol[i]]);
            cp_async16(st + 16384u + dstoff[i], &B[(size_t)(n0 + grow[i]) * Kd + k0 + gcol[i]]);
        }
        cp_async_commit();
    }

    int stage = 0;           // stage holding tile `it`
    for (int it = 0; it < KI; ++it) {
        // issue tile it+2 into the free stage, then wait for tile it
        if (it + 2 < KI) {
            int fs = stage + 2; if (fs >= 3) fs -= 3;
            const uint32_t st = sbase + fs * 32768u;
            const int k0 = (it + 2) << 5;
#pragma unroll
            for (int i = 0; i < 4; ++i) {
                cp_async16(st + dstoff[i],          &A[(size_t)(m0 + grow[i]) * Kd + k0 + gcol[i]]);
                cp_async16(st + 16384u + dstoff[i], &B[(size_t)(n0 + grow[i]) * Kd + k0 + gcol[i]]);
            }
            cp_async_commit();
            cp_async_wait<2>();
        } else if (it + 1 < KI) {
            cp_async_wait<1>();
        } else {
            cp_async_wait<0>();
        }
        __syncthreads();

        const uint32_t aBase = sbase + stage * 32768u;
        const uint32_t bBase = aBase + 16384u;
#pragma unroll
        for (int ks = 0; ks < 4; ++ks) {
            const uint32_t cOff = (uint32_t)((ks * 2 + csel) * 16);
            uint32_t a[4][4], b[2][4];
#pragma unroll
            for (int mt = 0; mt < 4; ++mt)
                ldmatrix_x4(a[mt][0], a[mt][1], a[mt][2], a[mt][3],
                            aBase + rbA[mt] + (cOff ^ rxA[mt]));
#pragma unroll
            for (int np = 0; np < 2; ++np)
                ldmatrix_x4(b[np][0], b[np][1], b[np][2], b[np][3],
                            bBase + rbB[np] + (cOff ^ rxB[np]));
            // operands are pre-rounded tf32 — no conversion needed
#pragma unroll
            for (int mt = 0; mt < 4; ++mt)
#pragma unroll
                for (int nt = 0; nt < 4; ++nt) {
                    const int np = nt >> 1, pos = nt & 1;
                    mma_tf32(acc[mt][nt], a[mt], b[np][pos], b[np][pos + 2]);
                }
        }
        __syncthreads();
        ++stage; if (stage == 3) stage = 0;
    }

    // ---- epilogue ----
    const int gq = lane >> 2;     // groupID
    const int tg = lane & 3;      // thread in group
#pragma unroll
    for (int mt = 0; mt < 4; ++mt) {
        const int r0 = m0 + warp_m * 64 + mt * 16 + gq;
#pragma unroll
        for (int nt = 0; nt < 4; ++nt) {
            const int c = n0 + warp_n * 32 + nt * 8 + tg * 2;
            float2 v0, v1;
            if (ROUND_OUT) {
                v0.x = roundtf(alpha * acc[mt][nt][0]); v0.y = roundtf(alpha * acc[mt][nt][1]);
                v1.x = roundtf(alpha * acc[mt][nt][2]); v1.y = roundtf(alpha * acc[mt][nt][3]);
            } else {
                v0.x = alpha * acc[mt][nt][0]; v0.y = alpha * acc[mt][nt][1];
                v1.x = alpha * acc[mt][nt][2]; v1.y = alpha * acc[mt][nt][3];
            }
            *reinterpret_cast<float2*>(&C[(size_t)r0 * Nn + c]) = v0;
            *reinterpret_cast<float2*>(&C[(size_t)(r0 + 8) * Nn + c]) = v1;
        }
    }
}

// ---------------------------------------------------------------------------
// round f32 -> tf32 (RNA), elementwise
// ---------------------------------------------------------------------------
__global__ __launch_bounds__(256)
void round_tf32_kernel(const float* __restrict__ in, float* __restrict__ out,
                       int n4)
{
    const int i = blockIdx.x * 256 + threadIdx.x;
    if (i < n4) {
        float4 v = reinterpret_cast<const float4*>(in)[i];
        v.x = roundtf(v.x); v.y = roundtf(v.y);
        v.z = roundtf(v.z); v.w = roundtf(v.w);
        reinterpret_cast<float4*>(out)[i] = v;
    }
}

// ---------------------------------------------------------------------------
// transpose + tf32 round: out[C][R] = round(in[R][C])
// ---------------------------------------------------------------------------
__global__ __launch_bounds__(256)
void transpose_kernel(const float* __restrict__ in, float* __restrict__ out,
                      int R, int C)
{
    __shared__ float tile[32][33];
    const int c0 = blockIdx.x * 32;
    const int r0 = blockIdx.y * 32;
    const int tx = threadIdx.x, ty = threadIdx.y;
#pragma unroll
    for (int i = ty; i < 32; i += 8)
        tile[i][tx] = roundtf(in[(size_t)(r0 + i) * C + c0 + tx]);
    __syncthreads();
#pragma unroll
    for (int i = ty; i < 32; i += 8)
        out[(size_t)(c0 + i) * R + r0 + tx] = tile[tx][i];
}

// ---------------------------------------------------------------------------
// Row softmax in place (+ tf32 rounding of the normalized weights)
// ---------------------------------------------------------------------------
__global__ __launch_bounds__(256)
void softmax_rows_kernel(float* __restrict__ S, int Nn)
{
    __shared__ float red[32];
    const int row = blockIdx.x;
    float* p = S + (size_t)row * Nn;
    const int t = threadIdx.x;
    const int lane = t & 31, wid = t >> 5;

    float m = -INFINITY;
    for (int i = t * 4; i < Nn; i += 256 * 4) {
        const float4 v = *reinterpret_cast<const float4*>(p + i);
        m = fmaxf(m, fmaxf(fmaxf(v.x, v.y), fmaxf(v.z, v.w)));
    }
#pragma unroll
    for (int o = 16; o > 0; o >>= 1) m = fmaxf(m, __shfl_xor_sync(0xffffffff, m, o));
    if (lane == 0) red[wid] = m;
    __syncthreads();
    if (t < 32) {
        float v = (t < 8) ? red[t] : -INFINITY;
#pragma unroll
        for (int o = 4; o > 0; o >>= 1) v = fmaxf(v, __shfl_xor_sync(0xffffffff, v, o));
        if (t == 0) red[0] = v;
    }
    __syncthreads();
    m = red[0];
    __syncthreads();

    float s = 0.f;
    for (int i = t * 4; i < Nn; i += 256 * 4) {
        float4 v = *reinterpret_cast<const float4*>(p + i);
        v.x = __expf(v.x - m); v.y = __expf(v.y - m);
        v.z = __expf(v.z - m); v.w = __expf(v.w - m);
        s += v.x + v.y + v.z + v.w;
        *reinterpret_cast<float4*>(p + i) = v;
    }
#pragma unroll
    for (int o = 16; o > 0; o >>= 1) s += __shfl_xor_sync(0xffffffff, s, o);
    if (lane == 0) red[wid] = s;
    __syncthreads();
    if (t < 32) {
        float v = (t < 8) ? red[t] : 0.f;
#pragma unroll
        for (int o = 4; o > 0; o >>= 1) v += __shfl_xor_sync(0xffffffff, v, o);
        if (t == 0) red[0] = v;
    }
    __syncthreads();
    const float inv = 1.f / red[0];

    for (int i = t * 4; i < Nn; i += 256 * 4) {
        float4 v = *reinterpret_cast<const float4*>(p + i);
        v.x = roundtf(v.x * inv); v.y = roundtf(v.y * inv);
        v.z = roundtf(v.z * inv); v.w = roundtf(v.w * inv);
        *reinterpret_cast<float4*>(p + i) = v;
    }
}

// ---------------------------------------------------------------------------
extern "C" void kernel_launch(void* const* d_in, const int* in_sizes, int n_in,
                              void* d_out, int out_size)
{
    const float* x  = (const float*)d_in[0];
    const float* Wq = (const float*)d_in[1];
    const float* Wk = (const float*)d_in[2];
    const float* Wv = (const float*)d_in[3];
    float* out = (float*)d_out;

    float *Xr, *Q, *K, *V, *S, *Wqt, *Wkt, *Wvt, *Vt;
    cudaGetSymbolAddress((void**)&Xr, g_Xr);
    cudaGetSymbolAddress((void**)&Q, g_Q);
    cudaGetSymbolAddress((void**)&K, g_K);
    cudaGetSymbolAddress((void**)&V, g_V);
    cudaGetSymbolAddress((void**)&S, g_S);
    cudaGetSymbolAddress((void**)&Wqt, g_Wqt);
    cudaGetSymbolAddress((void**)&Wkt, g_Wkt);
    cudaGetSymbolAddress((void**)&Wvt, g_Wvt);
    cudaGetSymbolAddress((void**)&Vt, g_Vt);

    cudaFuncSetAttribute(gemm_tf32_mma_kernel<true>,
                         cudaFuncAttributeMaxDynamicSharedMemorySize, GEMM_SMEM_TOTAL);
    cudaFuncSetAttribute(gemm_tf32_mma_kernel<false>,
                         cudaFuncAttributeMaxDynamicSharedMemorySize, GEMM_SMEM_TOTAL);

    const dim3 tblk(32, 8);

    // pre-round x
    {
        const int n4 = N_TOK * D_DIM / 4;
        round_tf32_kernel<<<(n4 + 255) / 256, 256>>>(x, Xr, n4);
    }

    // transpose + round weights: Wt[d_out][d_in]
    {
        const dim3 tg(D_DIM / 32, D_DIM / 32);
        transpose_kernel<<<tg, tblk>>>(Wq, Wqt, D_DIM, D_DIM);
        transpose_kernel<<<tg, tblk>>>(Wk, Wkt, D_DIM, D_DIM);
        transpose_kernel<<<tg, tblk>>>(Wv, Wvt, D_DIM, D_DIM);
    }

    // QKV projections, batched into one launch (z = 0,1,2), outputs tf32-rounded
    {
        const dim3 g(D_DIM / 128, N_TOK / 128, 3);
        gemm_tf32_mma_kernel<true><<<g, 256, GEMM_SMEM_TOTAL>>>(
            Xr, Wqt, Wkt, Wvt, Q, K, V, N_TOK, D_DIM, D_DIM, 1.f);
    }

    // Vt[d][token] (round idempotent)
    {
        const dim3 tg(D_DIM / 32, N_TOK / 32);
        transpose_kernel<<<tg, tblk>>>(V, Vt, N_TOK, D_DIM);
    }

    // S = round((Q @ K^T) / 32)
    {
        const dim3 g(N_TOK / 128, N_TOK / 128, 1);
        gemm_tf32_mma_kernel<true><<<g, 256, GEMM_SMEM_TOTAL>>>(
            Q, K, K, K, S, S, S, N_TOK, N_TOK, D_DIM, 1.f / 32.f);
    }

    softmax_rows_kernel<<<N_TOK, 256>>>(S, N_TOK);

    // out = P @ V  (full fp32 output)
    {
        const dim3 g(D_DIM / 128, N_TOK / 128, 1);
        gemm_tf32_mma_kernel<false><<<g, 256, GEMM_SMEM_TOTAL>>>(
            S, Vt, Vt, Vt, out, out, out, N_TOK, D_DIM, N_TOK, 1.f);
    }
}